// round 7
// baseline (speedup 1.0000x reference)
#include <cuda_runtime.h>
#include <cuda_bf16.h>
#include <cstdint>
#include <cstddef>

// Problem constants
#define Bn   16
#define Ln   1024
#define DIMn 1024
#define NH   16
#define DK   64

#define OUT_ELEMS    (16*1024*1024)
#define ATTNS_ELEMS  (16*8*1024*1024)
#define ATTNF_ELEMS  (16*8*64*64)

// fp32 scratch (head-major Qh/Kh/Vh, concat buffer)
__device__ float g_qh[OUT_ELEMS];
__device__ float g_kh[OUT_ELEMS];
__device__ float g_vh[OUT_ELEMS];
__device__ float g_cat[OUT_ELEMS];
// bf16 split scratch (reused across the 4 GEMMs)
__device__ __nv_bfloat16 g_ahi[OUT_ELEMS];
__device__ __nv_bfloat16 g_alo[OUT_ELEMS];
__device__ __nv_bfloat16 g_whi[DIMn*DIMn];
__device__ __nv_bfloat16 g_wlo[DIMn*DIMn];

// ===========================================================================
// Common helpers
// ===========================================================================
#define CP_ASYNC16(dst, src) \
    asm volatile("cp.async.cg.shared.global [%0], [%1], 16;\n" :: "r"(dst), "l"(src))
#define CP_COMMIT() asm volatile("cp.async.commit_group;\n" ::: "memory")
#define CP_WAIT(n)  asm volatile("cp.async.wait_group %0;\n" :: "n"(n) : "memory")

#define LDSM_X4(r0, r1, r2, r3, addr) \
    asm volatile("ldmatrix.sync.aligned.m8n8.x4.shared.b16 {%0,%1,%2,%3}, [%4];" \
                 : "=r"(r0), "=r"(r1), "=r"(r2), "=r"(r3) : "r"(addr))
#define LDSM_X2(r0, r1, addr) \
    asm volatile("ldmatrix.sync.aligned.m8n8.x2.shared.b16 {%0,%1}, [%2];" \
                 : "=r"(r0), "=r"(r1) : "r"(addr))
#define LDSM_X2_T(r0, r1, addr) \
    asm volatile("ldmatrix.sync.aligned.m8n8.x2.trans.shared.b16 {%0,%1}, [%2];" \
                 : "=r"(r0), "=r"(r1) : "r"(addr))

__device__ __forceinline__ void mma_bf16(float c[4], const uint32_t a[4], const uint32_t b[2]) {
    asm volatile(
        "mma.sync.aligned.m16n8k16.row.col.f32.bf16.bf16.f32 "
        "{%0,%1,%2,%3}, {%4,%5,%6,%7}, {%8,%9}, {%0,%1,%2,%3};\n"
        : "+f"(c[0]), "+f"(c[1]), "+f"(c[2]), "+f"(c[3])
        : "r"(a[0]), "r"(a[1]), "r"(a[2]), "r"(a[3]), "r"(b[0]), "r"(b[1]));
}

static __device__ __forceinline__ void split_pack(float x0, float x1,
                                                  uint32_t& hi, uint32_t& lo) {
    __nv_bfloat16 h0 = __float2bfloat16(x0);
    __nv_bfloat16 h1 = __float2bfloat16(x1);
    __nv_bfloat16 l0 = __float2bfloat16(x0 - __bfloat162float(h0));
    __nv_bfloat16 l1 = __float2bfloat16(x1 - __bfloat162float(h1));
    __nv_bfloat162 hp(h0, h1), lp(l0, l1);
    hi = *reinterpret_cast<uint32_t*>(&hp);
    lo = *reinterpret_cast<uint32_t*>(&lp);
}

// ===========================================================================
// Split kernels (fp32 -> bf16 hi/lo)
// ===========================================================================
__global__ __launch_bounds__(256) void split_a_k(
    const float* __restrict__ X, __nv_bfloat16* __restrict__ hi,
    __nv_bfloat16* __restrict__ lo)
{
    int i = (blockIdx.x * 256 + threadIdx.x) * 4;
    float4 v = *(const float4*)(X + i);
    float x[4] = {v.x, v.y, v.z, v.w};
    __nv_bfloat16 h[4], l[4];
    #pragma unroll
    for (int j = 0; j < 4; j++) {
        h[j] = __float2bfloat16(x[j]);
        l[j] = __float2bfloat16(x[j] - __bfloat162float(h[j]));
    }
    __nv_bfloat162* hp = (__nv_bfloat162*)(hi + i);
    __nv_bfloat162* lp = (__nv_bfloat162*)(lo + i);
    hp[0] = __nv_bfloat162{h[0], h[1]}; hp[1] = __nv_bfloat162{h[2], h[3]};
    lp[0] = __nv_bfloat162{l[0], l[1]}; lp[1] = __nv_bfloat162{l[2], l[3]};
}

__global__ __launch_bounds__(256) void split_w_k(
    const float* __restrict__ W, __nv_bfloat16* __restrict__ hi,
    __nv_bfloat16* __restrict__ lo)
{
    __shared__ float t[32][33];
    const int tx = threadIdx.x, ty = threadIdx.y;
    const int n0 = blockIdx.x * 32, k0 = blockIdx.y * 32;
    #pragma unroll
    for (int j = 0; j < 32; j += 8)
        t[ty + j][tx] = W[(size_t)(k0 + ty + j) * DIMn + n0 + tx];
    __syncthreads();
    #pragma unroll
    for (int j = 0; j < 32; j += 8) {
        int n = n0 + ty + j, kk = k0 + tx;
        float x = t[tx][ty + j];
        __nv_bfloat16 h = __float2bfloat16(x);
        __nv_bfloat16 l = __float2bfloat16(x - __bfloat162float(h));
        hi[(size_t)n * DIMn + kk] = h;
        lo[(size_t)n * DIMn + kk] = l;
    }
}

// ===========================================================================
// Split-bf16 mma.sync GEMM, CTA 256x256, 512 threads, 16 warps (4x4),
// warp tile 64x64, BK=32. acc += Ah*Bh + Ah*Bl + Al*Bh.
// Smem rows 80B (40 bf16), 2-stage cp.async, occ 1.
// MODE 0: row-major C; MODE 1: head-major C.
// ===========================================================================
#define TILB2   (256*80)            // 20480 B per operand tile
#define STAGE2  (4*TILB2)           // Ahi,Alo,Bhi,Blo = 81920
#define GSMEM2  (2*STAGE2)          // 163840

template<int MODE>
__global__ __launch_bounds__(512, 1) void gemm_lm_k(
    const __nv_bfloat16* __restrict__ Ahi, const __nv_bfloat16* __restrict__ Alo,
    const __nv_bfloat16* __restrict__ Bhi, const __nv_bfloat16* __restrict__ Blo,
    float* __restrict__ C)
{
    extern __shared__ char smem[];
    uint32_t sb;
    asm("{ .reg .u64 u; cvta.to.shared.u64 u, %1; cvt.u32.u64 %0, u; }" : "=r"(sb) : "l"(smem));

    const int tid  = threadIdx.x;
    const int lane = tid & 31;
    const int warp = tid >> 5;
    const int wm   = warp >> 2;    // 0..3
    const int wn   = warp & 3;     // 0..3
    const int g    = lane >> 2;    // 0..7
    const int t4   = lane & 3;     // 0..3

    const int row0 = blockIdx.y * 256;
    const int col0 = blockIdx.x * 256;

    const int sub = lane >> 3, r8 = lane & 7;
    const uint32_t loffA = (uint32_t)((r8 + (sub & 1) * 8) * 80 + (sub >> 1) * 16);
    const uint32_t loffB = (uint32_t)((r8 + (sub >> 1) * 8) * 80 + (sub & 1) * 16);

    // cp.async mapping: per tile 256 rows x 4 chunks(16B) = 1024; thread does
    // idx = tid and tid+512.
    const int r_0 = tid >> 2, ch0 = tid & 3;
    const int r_1 = (tid + 512) >> 2, ch1 = ch0;

    auto prefetch = [&](int c, int st) {
        const int kc = c * 32;
        uint32_t s0 = sb + (uint32_t)st * STAGE2;
        {
            uint32_t d = s0 + (uint32_t)(r_0 * 80 + ch0 * 16);
            size_t ga = ((size_t)(row0 + r_0) * 1024 + kc + ch0 * 8) * 2;
            size_t gb = ((size_t)(col0 + r_0) * 1024 + kc + ch0 * 8) * 2;
            CP_ASYNC16(d,             (const char*)Ahi + ga);
            CP_ASYNC16(d + TILB2,     (const char*)Alo + ga);
            CP_ASYNC16(d + 2*TILB2,   (const char*)Bhi + gb);
            CP_ASYNC16(d + 3*TILB2,   (const char*)Blo + gb);
        }
        {
            uint32_t d = s0 + (uint32_t)(r_1 * 80 + ch1 * 16);
            size_t ga = ((size_t)(row0 + r_1) * 1024 + kc + ch1 * 8) * 2;
            size_t gb = ((size_t)(col0 + r_1) * 1024 + kc + ch1 * 8) * 2;
            CP_ASYNC16(d,             (const char*)Ahi + ga);
            CP_ASYNC16(d + TILB2,     (const char*)Alo + ga);
            CP_ASYNC16(d + 2*TILB2,   (const char*)Bhi + gb);
            CP_ASYNC16(d + 3*TILB2,   (const char*)Blo + gb);
        }
    };

    float acc[4][8][4];
    #pragma unroll
    for (int mt = 0; mt < 4; mt++)
        #pragma unroll
        for (int nt = 0; nt < 8; nt++)
            #pragma unroll
            for (int i = 0; i < 4; i++) acc[mt][nt][i] = 0.f;

    prefetch(0, 0); CP_COMMIT();
    prefetch(1, 1); CP_COMMIT();

    const int nk = 32;
    for (int c = 0; c < nk; c++) {
        const int st = c & 1;
        if (c + 1 < nk) { CP_WAIT(1); } else { CP_WAIT(0); }
        __syncthreads();

        const uint32_t s0 = sb + (uint32_t)st * STAGE2;
        const uint32_t aB = s0 + (uint32_t)(wm * 64) * 80;
        const uint32_t bB = s0 + 2 * TILB2 + (uint32_t)(wn * 64) * 80;

        #pragma unroll
        for (int ks = 0; ks < 2; ks++) {
            const uint32_t kb = ks * 32;
            uint32_t bh[8][2], bl[8][2];
            #pragma unroll
            for (int p = 0; p < 4; p++) {
                uint32_t base = bB + (uint32_t)(p * 16) * 80 + kb;
                LDSM_X4(bh[2*p][0], bh[2*p][1], bh[2*p+1][0], bh[2*p+1][1], base + loffB);
                LDSM_X4(bl[2*p][0], bl[2*p][1], bl[2*p+1][0], bl[2*p+1][1], base + TILB2 + loffB);
            }
            #pragma unroll
            for (int mt = 0; mt < 4; mt++) {
                uint32_t abase = aB + (uint32_t)(mt * 16) * 80 + kb;
                uint32_t ah[4], al[4];
                LDSM_X4(ah[0], ah[1], ah[2], ah[3], abase + loffA);
                LDSM_X4(al[0], al[1], al[2], al[3], abase + TILB2 + loffA);
                #pragma unroll
                for (int nt = 0; nt < 8; nt++) {
                    mma_bf16(acc[mt][nt], ah, bh[nt]);
                    mma_bf16(acc[mt][nt], ah, bl[nt]);
                    mma_bf16(acc[mt][nt], al, bh[nt]);
                }
            }
        }
        __syncthreads();
        if (c + 2 < nk) { prefetch(c + 2, st); CP_COMMIT(); }
    }

    #pragma unroll
    for (int mt = 0; mt < 4; mt++) {
        #pragma unroll
        for (int nt = 0; nt < 8; nt++) {
            int r = row0 + wm * 64 + mt * 16 + g;
            int c = col0 + wn * 64 + nt * 8 + 2 * t4;
            float2 v0 = make_float2(acc[mt][nt][0], acc[mt][nt][1]);
            float2 v1 = make_float2(acc[mt][nt][2], acc[mt][nt][3]);
            if (MODE == 0) {
                *(float2*)(C + (size_t)r * 1024 + c)       = v0;
                *(float2*)(C + (size_t)(r + 8) * 1024 + c) = v1;
            } else {
                int b_ = r >> 10, l0 = r & 1023;
                int h_ = c >> 6,  d_ = c & 63;
                size_t base = ((size_t)(b_ * 16 + h_) * 1024) * 64 + d_;
                *(float2*)(C + base + (size_t)l0 * 64)       = v0;
                *(float2*)(C + base + (size_t)(l0 + 8) * 64) = v1;
            }
        }
    }
}

// ===========================================================================
// Even-head attention, tensor-core version (unchanged from R6, passing).
// ===========================================================================
#define SSTR 1032
#define AE_QS   132096
#define AE_KV   140800
#define AE_KVST 18432
#define AE_TL   9216
#define AE_P    177664
#define AE_PST  9216
#define AE_PTL  4608
#define SMEM_EVEN 196096

__global__ __launch_bounds__(512) void attn_even_k(
    const float* __restrict__ Qh, const float* __restrict__ Kh,
    const float* __restrict__ Vh, const float* __restrict__ mask_s,
    float* __restrict__ attn_s, float* __restrict__ out_cat)
{
    extern __shared__ char smem[];
    float* Ssm = (float*)smem;
    float* Qs  = (float*)(smem + AE_QS);
    uint32_t sb;
    asm("{ .reg .u64 u; cvta.to.shared.u64 u, %1; cvt.u32.u64 %0, u; }" : "=r"(sb) : "l"(smem));

    const int qt = blockIdx.x, j = blockIdx.y, b = blockIdx.z;
    const int h = 2 * j;
    const int tid = threadIdx.x;
    const int warp = tid >> 5, lane = tid & 31;
    const int g = lane >> 2, t4 = lane & 3;
    const int mt = warp >> 3, ntw = warp & 7;
    const int m0 = mt * 16, n0 = ntw * 8;
    const size_t headoff = (size_t)(b * 16 + h) * 1024 * 64;
    const float* Qb = Qh + headoff;
    const float* Kb = Kh + headoff;
    const float* Vb = Vh + headoff;
    const int r0 = qt * 32;

    const int krow = tid >> 3, kcol8 = (tid & 7) * 8;
    const int pr = tid >> 4, pc = (tid & 15) * 4;

    {
        int r = tid >> 4, c = (tid & 15) * 4;
        float4 v = *(const float4*)(Qb + (size_t)(r0 + r) * 64 + c);
        *(float4*)&Qs[r * 68 + c] = v;
    }

    float4 fa, fb;
    fa = *(const float4*)(Kb + (size_t)krow * 64 + kcol8);
    fb = *(const float4*)(Kb + (size_t)krow * 64 + kcol8 + 4);
    __syncthreads();

    uint32_t qhF[4][4], qlF[4][4];
    #pragma unroll
    for (int ks = 0; ks < 4; ks++) {
        int kc = ks * 16 + 2 * t4;
        split_pack(Qs[(m0+g)*68 + kc],     Qs[(m0+g)*68 + kc + 1],     qhF[ks][0], qlF[ks][0]);
        split_pack(Qs[(m0+g+8)*68 + kc],   Qs[(m0+g+8)*68 + kc + 1],   qhF[ks][1], qlF[ks][1]);
        split_pack(Qs[(m0+g)*68 + kc + 8], Qs[(m0+g)*68 + kc + 9],     qhF[ks][2], qlF[ks][2]);
        split_pack(Qs[(m0+g+8)*68 + kc+8], Qs[(m0+g+8)*68 + kc + 9],   qhF[ks][3], qlF[ks][3]);
    }

    const int lrow = (lane & 7);
    const uint32_t lsel = (uint32_t)(((lane >> 3) & 1) * 16);

    for (int kt = 0; kt < 16; kt++) {
        const int st = kt & 1;
        {
            uint32_t hw0,hw1,hw2,hw3, lw0,lw1,lw2,lw3;
            split_pack(fa.x, fa.y, hw0, lw0);
            split_pack(fa.z, fa.w, hw1, lw1);
            split_pack(fb.x, fb.y, hw2, lw2);
            split_pack(fb.z, fb.w, hw3, lw3);
            char* dh = smem + AE_KV + st * AE_KVST + krow * 144 + kcol8 * 2;
            *(uint4*)dh            = make_uint4(hw0, hw1, hw2, hw3);
            *(uint4*)(dh + AE_TL)  = make_uint4(lw0, lw1, lw2, lw3);
        }
        if (kt < 15) {
            fa = *(const float4*)(Kb + (size_t)((kt+1)*64 + krow) * 64 + kcol8);
            fb = *(const float4*)(Kb + (size_t)((kt+1)*64 + krow) * 64 + kcol8 + 4);
        }
        __syncthreads();

        float accS[4] = {0.f, 0.f, 0.f, 0.f};
        const uint32_t kb_hi = sb + AE_KV + st * AE_KVST;
        #pragma unroll
        for (int ks = 0; ks < 4; ks++) {
            uint32_t addr = kb_hi + (uint32_t)(n0 + lrow) * 144 + ks * 32 + lsel;
            uint32_t bh[2], bl[2];
            LDSM_X2(bh[0], bh[1], addr);
            LDSM_X2(bl[0], bl[1], addr + AE_TL);
            mma_bf16(accS, qhF[ks], bh);
            mma_bf16(accS, qhF[ks], bl);
            mma_bf16(accS, qlF[ks], bh);
        }
        int cbase = kt * 64 + n0 + 2 * t4;
        *(float2*)&Ssm[(m0+g)*SSTR + cbase]   = make_float2(accS[0], accS[1]);
        *(float2*)&Ssm[(m0+g+8)*SSTR + cbase] = make_float2(accS[2], accS[3]);
    }
    __syncthreads();

    for (int rr = warp * 2; rr < warp * 2 + 2; rr++) {
        const int grow = r0 + rr;
        float* Srow = Ssm + rr * SSTR;
        const float* mrow = mask_s + (size_t)grow * 1024;
        float mx = -1e30f;
        for (int c = lane; c < 1024; c += 32) {
            float s = Srow[c] * 0.125f + mrow[c];
            Srow[c] = s;
            mx = fmaxf(mx, s);
        }
        #pragma unroll
        for (int o = 16; o > 0; o >>= 1) mx = fmaxf(mx, __shfl_xor_sync(0xffffffffu, mx, o));
        float sum = 0.f;
        for (int c = lane; c < 1024; c += 32) {
            float e = __expf(Srow[c] - mx);
            Srow[c] = e;
            sum += e;
        }
        #pragma unroll
        for (int o = 16; o > 0; o >>= 1) sum += __shfl_xor_sync(0xffffffffu, sum, o);
        float inv = 1.f / sum;
        float* arow = attn_s + ((size_t)(b * 8 + j) * 1024 + grow) * 1024;
        for (int c = lane; c < 1024; c += 32) {
            float p = Srow[c] * inv;
            Srow[c] = p;
            arow[c] = p;
        }
    }
    __syncthreads();

    float accO[4] = {0.f, 0.f, 0.f, 0.f};
    fa = *(const float4*)(Vb + (size_t)krow * 64 + kcol8);
    fb = *(const float4*)(Vb + (size_t)krow * 64 + kcol8 + 4);

    const int sub = lane >> 3, r8 = lane & 7;
    const uint32_t poff = (uint32_t)((m0 + r8 + (sub & 1) * 8) * 144 + (sub >> 1) * 16);
    const int vrow = (lane & 15);

    for (int kt = 0; kt < 16; kt++) {
        const int st = kt & 1;
        {
            uint32_t hw0,hw1,hw2,hw3, lw0,lw1,lw2,lw3;
            split_pack(fa.x, fa.y, hw0, lw0);
            split_pack(fa.z, fa.w, hw1, lw1);
            split_pack(fb.x, fb.y, hw2, lw2);
            split_pack(fb.z, fb.w, hw3, lw3);
            char* dh = smem + AE_KV + st * AE_KVST + krow * 144 + kcol8 * 2;
            *(uint4*)dh            = make_uint4(hw0, hw1, hw2, hw3);
            *(uint4*)(dh + AE_TL)  = make_uint4(lw0, lw1, lw2, lw3);
        }
        {
            float4 pv = *(const float4*)&Ssm[pr * SSTR + kt * 64 + pc];
            uint32_t h0, h1, l0, l1;
            split_pack(pv.x, pv.y, h0, l0);
            split_pack(pv.z, pv.w, h1, l1);
            char* dp = smem + AE_P + st * AE_PST + pr * 144 + pc * 2;
            *(uint2*)dp            = make_uint2(h0, h1);
            *(uint2*)(dp + AE_PTL) = make_uint2(l0, l1);
        }
        if (kt < 15) {
            fa = *(const float4*)(Vb + (size_t)((kt+1)*64 + krow) * 64 + kcol8);
            fb = *(const float4*)(Vb + (size_t)((kt+1)*64 + krow) * 64 + kcol8 + 4);
        }
        __syncthreads();

        const uint32_t pb_hi = sb + AE_P + st * AE_PST;
        const uint32_t vb_hi = sb + AE_KV + st * AE_KVST;
        #pragma unroll
        for (int ks = 0; ks < 4; ks++) {
            uint32_t ph[4], pl[4];
            LDSM_X4(ph[0], ph[1], ph[2], ph[3], pb_hi + poff + ks * 32);
            LDSM_X4(pl[0], pl[1], pl[2], pl[3], pb_hi + AE_PTL + poff + ks * 32);
            uint32_t vh[2], vl[2];
            uint32_t vaddr = vb_hi + (uint32_t)(ks * 16 + vrow) * 144 + n0 * 2;
            LDSM_X2_T(vh[0], vh[1], vaddr);
            LDSM_X2_T(vl[0], vl[1], vaddr + AE_TL);
            mma_bf16(accO, ph, vh);
            mma_bf16(accO, ph, vl);
            mma_bf16(accO, pl, vh);
        }
    }

    {
        int c = j * 64 + n0 + 2 * t4;
        *(float2*)(out_cat + ((size_t)b * 1024 + r0 + m0 + g) * 1024 + c)     = make_float2(accO[0], accO[1]);
        *(float2*)(out_cat + ((size_t)b * 1024 + r0 + m0 + g + 8) * 1024 + c) = make_float2(accO[2], accO[3]);
    }
}

// ---------------------------------------------------------------------------
// Odd-head "feature" attention (unchanged).
// ---------------------------------------------------------------------------
#define SMEM_FEAT ((2*64*64 + 64*65) * 4)
__global__ __launch_bounds__(256) void attn_feat_k(
    const float* __restrict__ Qh, const float* __restrict__ Kh,
    const float* __restrict__ Vh, const float* __restrict__ mask_f,
    float* __restrict__ attn_f, float* __restrict__ out_cat)
{
    extern __shared__ float sm[];
    float* Qt  = sm;
    float* Kt  = Qt + 4096;
    float* Asm = Kt + 4096;

    const int jp = blockIdx.x, b = blockIdx.y;
    const int h = 2 * jp + 1;
    const int tid = threadIdx.x;
    const size_t headoff = (size_t)(b * 16 + h) * 1024 * 64;
    const float* Qb = Qh + headoff;
    const float* Kb = Kh + headoff;
    const float* Vb = Vh + headoff;

    const int m  = tid & 63;
    const int g4 = tid >> 6;

    float acc[16];
    #pragma unroll
    for (int i = 0; i < 16; i++) acc[i] = 0.f;

    for (int lt = 0; lt < 16; lt++) {
        __syncthreads();
        for (int i = tid; i < 1024; i += 256) {
            ((float4*)Qt)[i] = ((const float4*)(Qb + (size_t)lt * 4096))[i];
            ((float4*)Kt)[i] = ((const float4*)(Kb + (size_t)lt * 4096))[i];
        }
        __syncthreads();
        for (int ll = 0; ll < 64; ll++) {
            float kk = Kt[ll * 64 + m];
            #pragma unroll
            for (int i = 0; i < 16; i++)
                acc[i] = fmaf(Qt[ll * 64 + g4 + 4 * i], kk, acc[i]);
        }
    }
    __syncthreads();
    #pragma unroll
    for (int i = 0; i < 16; i++) {
        int n = g4 + 4 * i;
        Asm[n * 65 + m] = acc[i] * 0.125f + mask_f[n * 64 + m];
    }
    __syncthreads();

    const int warp = tid >> 5, lane = tid & 31;
    for (int n = warp * 8; n < warp * 8 + 8; n++) {
        float* row = Asm + n * 65;
        float a0 = row[lane], a1 = row[lane + 32];
        float mx = fmaxf(a0, a1);
        #pragma unroll
        for (int o = 16; o > 0; o >>= 1) mx = fmaxf(mx, __shfl_xor_sync(0xffffffffu, mx, o));
        float e0 = __expf(a0 - mx), e1 = __expf(a1 - mx);
        float s = e0 + e1;
        #pragma unroll
        for (int o = 16; o > 0; o >>= 1) s += __shfl_xor_sync(0xffffffffu, s, o);
        float inv = 1.f / s;
        e0 *= inv; e1 *= inv;
        row[lane] = e0; row[lane + 32] = e1;
        float* grow = attn_f + ((size_t)(b * 8 + jp) * 64 + n) * 64;
        grow[lane] = e0; grow[lane + 32] = e1;
    }
    __syncthreads();

    float* Vt = Qt;
    const int n2 = m;
    for (int lt = 0; lt < 16; lt++) {
        __syncthreads();
        for (int i = tid; i < 1024; i += 256)
            ((float4*)Vt)[i] = ((const float4*)(Vb + (size_t)lt * 4096))[i];
        __syncthreads();

        float accO[16];
        #pragma unroll
        for (int i = 0; i < 16; i++) accO[i] = 0.f;
        for (int mm = 0; mm < 64; mm++) {
            float aa = Asm[n2 * 65 + mm];
            #pragma unroll
            for (int i = 0; i < 16; i++)
                accO[i] = fmaf(Vt[(g4 + 4 * i) * 64 + mm], aa, accO[i]);
        }
        #pragma unroll
        for (int i = 0; i < 16; i++) {
            int ll = g4 + 4 * i;
            out_cat[((size_t)b * 1024 + lt * 64 + ll) * 1024 + (8 + jp) * 64 + n2] = accO[i];
        }
    }
}

// ---------------------------------------------------------------------------
extern "C" void kernel_launch(void* const* d_in, const int* in_sizes, int n_in,
                              void* d_out, int out_size)
{
    const float* q      = (const float*)d_in[0];
    const float* k      = (const float*)d_in[1];
    const float* v      = (const float*)d_in[2];
    const float* mask_s = (const float*)d_in[3];
    const float* mask_f = (const float*)d_in[4];
    const float* Wq     = (const float*)d_in[5];
    const float* Wk     = (const float*)d_in[6];
    const float* Wv     = (const float*)d_in[7];
    const float* Wo     = (const float*)d_in[8];

    float* out    = (float*)d_out;
    float* attn_s = out + OUT_ELEMS;
    float* attn_f = attn_s + ATTNS_ELEMS;

    float *qh, *kh, *vh, *cat;
    __nv_bfloat16 *ahi, *alo, *whi, *wlo;
    cudaGetSymbolAddress((void**)&qh,  g_qh);
    cudaGetSymbolAddress((void**)&kh,  g_kh);
    cudaGetSymbolAddress((void**)&vh,  g_vh);
    cudaGetSymbolAddress((void**)&cat, g_cat);
    cudaGetSymbolAddress((void**)&ahi, g_ahi);
    cudaGetSymbolAddress((void**)&alo, g_alo);
    cudaGetSymbolAddress((void**)&whi, g_whi);
    cudaGetSymbolAddress((void**)&wlo, g_wlo);

    cudaFuncSetAttribute(attn_even_k, cudaFuncAttributeMaxDynamicSharedMemorySize, SMEM_EVEN);
    cudaFuncSetAttribute(attn_feat_k, cudaFuncAttributeMaxDynamicSharedMemorySize, SMEM_FEAT);
    cudaFuncSetAttribute(gemm_lm_k<0>, cudaFuncAttributeMaxDynamicSharedMemorySize, GSMEM2);
    cudaFuncSetAttribute(gemm_lm_k<1>, cudaFuncAttributeMaxDynamicSharedMemorySize, GSMEM2);

    dim3 ggrid(DIMn / 256, (Bn * Ln) / 256);  // (4, 64)
    dim3 sgrid(OUT_ELEMS / (256 * 4));
    dim3 wgrid(32, 32), wblk(32, 8);

    // Q projection
    split_a_k<<<sgrid, 256>>>(q, ahi, alo);
    split_w_k<<<wgrid, wblk>>>(Wq, whi, wlo);
    gemm_lm_k<1><<<ggrid, 512, GSMEM2>>>(ahi, alo, whi, wlo, qh);
    // K projection
    split_a_k<<<sgrid, 256>>>(k, ahi, alo);
    split_w_k<<<wgrid, wblk>>>(Wk, whi, wlo);
    gemm_lm_k<1><<<ggrid, 512, GSMEM2>>>(ahi, alo, whi, wlo, kh);
    // V projection
    split_a_k<<<sgrid, 256>>>(v, ahi, alo);
    split_w_k<<<wgrid, wblk>>>(Wv, whi, wlo);
    gemm_lm_k<1><<<ggrid, 512, GSMEM2>>>(ahi, alo, whi, wlo, vh);

    // Attention
    attn_even_k<<<dim3(32, 8, 16), 512, SMEM_EVEN>>>(qh, kh, vh, mask_s, attn_s, cat);
    attn_feat_k<<<dim3(8, 16), 256, SMEM_FEAT>>>(qh, kh, vh, mask_f, attn_f, cat);

    // Output projection
    split_a_k<<<sgrid, 256>>>(cat, ahi, alo);
    split_w_k<<<wgrid, wblk>>>(Wo, whi, wlo);
    gemm_lm_k<0><<<ggrid, 512, GSMEM2>>>(ahi, alo, whi, wlo, out);
}

// round 8
// speedup vs baseline: 1.6541x; 1.6541x over previous
#include <cuda_runtime.h>
#include <cuda_bf16.h>
#include <cstdint>
#include <cstddef>

// Problem constants
#define Bn   16
#define Ln   1024
#define DIMn 1024
#define NH   16
#define DK   64

#define OUT_ELEMS    (16*1024*1024)
#define ATTNS_ELEMS  (16*8*1024*1024)
#define ATTNF_ELEMS  (16*8*64*64)

// fp32 scratch (head-major Qh/Kh/Vh, concat buffer)
__device__ float g_qh[OUT_ELEMS];
__device__ float g_kh[OUT_ELEMS];
__device__ float g_vh[OUT_ELEMS];
__device__ float g_cat[OUT_ELEMS];
// bf16 split scratch: 3 activation tensors (q,k,v) + 3 weights upfront
__device__ __nv_bfloat16 g_ahi3[3*OUT_ELEMS];
__device__ __nv_bfloat16 g_alo3[3*OUT_ELEMS];
__device__ __nv_bfloat16 g_whi3[3*DIMn*DIMn];
__device__ __nv_bfloat16 g_wlo3[3*DIMn*DIMn];

// ===========================================================================
// Common helpers
// ===========================================================================
#define CP_ASYNC16(dst, src) \
    asm volatile("cp.async.cg.shared.global [%0], [%1], 16;\n" :: "r"(dst), "l"(src))
#define CP_COMMIT() asm volatile("cp.async.commit_group;\n" ::: "memory")
#define CP_WAIT(n)  asm volatile("cp.async.wait_group %0;\n" :: "n"(n) : "memory")

#define LDSM_X4(r0, r1, r2, r3, addr) \
    asm volatile("ldmatrix.sync.aligned.m8n8.x4.shared.b16 {%0,%1,%2,%3}, [%4];" \
                 : "=r"(r0), "=r"(r1), "=r"(r2), "=r"(r3) : "r"(addr))
#define LDSM_X2(r0, r1, addr) \
    asm volatile("ldmatrix.sync.aligned.m8n8.x2.shared.b16 {%0,%1}, [%2];" \
                 : "=r"(r0), "=r"(r1) : "r"(addr))
#define LDSM_X2_T(r0, r1, addr) \
    asm volatile("ldmatrix.sync.aligned.m8n8.x2.trans.shared.b16 {%0,%1}, [%2];" \
                 : "=r"(r0), "=r"(r1) : "r"(addr))

__device__ __forceinline__ void mma_bf16(float c[4], const uint32_t a[4], const uint32_t b[2]) {
    asm volatile(
        "mma.sync.aligned.m16n8k16.row.col.f32.bf16.bf16.f32 "
        "{%0,%1,%2,%3}, {%4,%5,%6,%7}, {%8,%9}, {%0,%1,%2,%3};\n"
        : "+f"(c[0]), "+f"(c[1]), "+f"(c[2]), "+f"(c[3])
        : "r"(a[0]), "r"(a[1]), "r"(a[2]), "r"(a[3]), "r"(b[0]), "r"(b[1]));
}

static __device__ __forceinline__ void split_pack(float x0, float x1,
                                                  uint32_t& hi, uint32_t& lo) {
    __nv_bfloat16 h0 = __float2bfloat16(x0);
    __nv_bfloat16 h1 = __float2bfloat16(x1);
    __nv_bfloat16 l0 = __float2bfloat16(x0 - __bfloat162float(h0));
    __nv_bfloat16 l1 = __float2bfloat16(x1 - __bfloat162float(h1));
    __nv_bfloat162 hp(h0, h1), lp(l0, l1);
    hi = *reinterpret_cast<uint32_t*>(&hp);
    lo = *reinterpret_cast<uint32_t*>(&lp);
}

// ===========================================================================
// Split kernels (fp32 -> bf16 hi/lo)
// ===========================================================================
// Merged activation split: blockIdx.y selects tensor 0..2 (q,k,v)
__global__ __launch_bounds__(256) void split_a3_k(
    const float* __restrict__ X0, const float* __restrict__ X1,
    const float* __restrict__ X2,
    __nv_bfloat16* __restrict__ hi, __nv_bfloat16* __restrict__ lo)
{
    const int t = blockIdx.y;
    const float* X = (t == 0) ? X0 : (t == 1) ? X1 : X2;
    size_t obase = (size_t)t * OUT_ELEMS;
    int i = (blockIdx.x * 256 + threadIdx.x) * 4;
    float4 v = *(const float4*)(X + i);
    float x[4] = {v.x, v.y, v.z, v.w};
    __nv_bfloat16 h[4], l[4];
    #pragma unroll
    for (int j = 0; j < 4; j++) {
        h[j] = __float2bfloat16(x[j]);
        l[j] = __float2bfloat16(x[j] - __bfloat162float(h[j]));
    }
    __nv_bfloat162* hp = (__nv_bfloat162*)(hi + obase + i);
    __nv_bfloat162* lp = (__nv_bfloat162*)(lo + obase + i);
    hp[0] = __nv_bfloat162{h[0], h[1]}; hp[1] = __nv_bfloat162{h[2], h[3]};
    lp[0] = __nv_bfloat162{l[0], l[1]}; lp[1] = __nv_bfloat162{l[2], l[3]};
}

// Single-tensor activation split (for cat)
__global__ __launch_bounds__(256) void split_a_k(
    const float* __restrict__ X, __nv_bfloat16* __restrict__ hi,
    __nv_bfloat16* __restrict__ lo)
{
    int i = (blockIdx.x * 256 + threadIdx.x) * 4;
    float4 v = *(const float4*)(X + i);
    float x[4] = {v.x, v.y, v.z, v.w};
    __nv_bfloat16 h[4], l[4];
    #pragma unroll
    for (int j = 0; j < 4; j++) {
        h[j] = __float2bfloat16(x[j]);
        l[j] = __float2bfloat16(x[j] - __bfloat162float(h[j]));
    }
    __nv_bfloat162* hp = (__nv_bfloat162*)(hi + i);
    __nv_bfloat162* lp = (__nv_bfloat162*)(lo + i);
    hp[0] = __nv_bfloat162{h[0], h[1]}; hp[1] = __nv_bfloat162{h[2], h[3]};
    lp[0] = __nv_bfloat162{l[0], l[1]}; lp[1] = __nv_bfloat162{l[2], l[3]};
}

// Merged weight split+transpose: blockIdx.z selects 0..2 (Wq,Wk,Wv)
__global__ __launch_bounds__(256) void split_w3_k(
    const float* __restrict__ W0, const float* __restrict__ W1,
    const float* __restrict__ W2,
    __nv_bfloat16* __restrict__ hi, __nv_bfloat16* __restrict__ lo)
{
    __shared__ float t[32][33];
    const int wz = blockIdx.z;
    const float* W = (wz == 0) ? W0 : (wz == 1) ? W1 : W2;
    size_t obase = (size_t)wz * DIMn * DIMn;
    const int tx = threadIdx.x, ty = threadIdx.y;
    const int n0 = blockIdx.x * 32, k0 = blockIdx.y * 32;
    #pragma unroll
    for (int j = 0; j < 32; j += 8)
        t[ty + j][tx] = W[(size_t)(k0 + ty + j) * DIMn + n0 + tx];
    __syncthreads();
    #pragma unroll
    for (int j = 0; j < 32; j += 8) {
        int n = n0 + ty + j, kk = k0 + tx;
        float x = t[tx][ty + j];
        __nv_bfloat16 h = __float2bfloat16(x);
        __nv_bfloat16 l = __float2bfloat16(x - __bfloat162float(h));
        hi[obase + (size_t)n * DIMn + kk] = h;
        lo[obase + (size_t)n * DIMn + kk] = l;
    }
}

// Single weight split+transpose (for Wo)
__global__ __launch_bounds__(256) void split_w_k(
    const float* __restrict__ W, __nv_bfloat16* __restrict__ hi,
    __nv_bfloat16* __restrict__ lo)
{
    __shared__ float t[32][33];
    const int tx = threadIdx.x, ty = threadIdx.y;
    const int n0 = blockIdx.x * 32, k0 = blockIdx.y * 32;
    #pragma unroll
    for (int j = 0; j < 32; j += 8)
        t[ty + j][tx] = W[(size_t)(k0 + ty + j) * DIMn + n0 + tx];
    __syncthreads();
    #pragma unroll
    for (int j = 0; j < 32; j += 8) {
        int n = n0 + ty + j, kk = k0 + tx;
        float x = t[tx][ty + j];
        __nv_bfloat16 h = __float2bfloat16(x);
        __nv_bfloat16 l = __float2bfloat16(x - __bfloat162float(h));
        hi[(size_t)n * DIMn + kk] = h;
        lo[(size_t)n * DIMn + kk] = l;
    }
}

// ===========================================================================
// Split-bf16 mma.sync GEMM (R6 geometry: CTA 128x128, 256 thr, 8 warps 64x32,
// BK=32, rows 80B, 2-stage cp.async, occ 2). PASSING CONFIG — do not touch.
// ===========================================================================
#define RS      40
#define TILB    (128*RS*2)
#define STAGEB  (4*TILB)
#define GSMEM   (2*STAGEB)

template<int MODE>
__global__ __launch_bounds__(256, 2) void gemm_lm_k(
    const __nv_bfloat16* __restrict__ Ahi, const __nv_bfloat16* __restrict__ Alo,
    const __nv_bfloat16* __restrict__ Bhi, const __nv_bfloat16* __restrict__ Blo,
    float* __restrict__ C)
{
    extern __shared__ char smem[];
    uint32_t sb;
    asm("{ .reg .u64 u; cvta.to.shared.u64 u, %1; cvt.u32.u64 %0, u; }" : "=r"(sb) : "l"(smem));

    const int tid  = threadIdx.x;
    const int lane = tid & 31;
    const int warp = tid >> 5;
    const int wm   = warp >> 2;
    const int wn   = warp & 3;
    const int g    = lane >> 2;
    const int t4   = lane & 3;

    const int row0 = blockIdx.y * 128;
    const int col0 = blockIdx.x * 128;

    const int sub = lane >> 3, r8 = lane & 7;
    const uint32_t loffA = (uint32_t)((r8 + (sub & 1) * 8) * 80 + (sub >> 1) * 16);
    const uint32_t loffB = (uint32_t)((r8 + (sub >> 1) * 8) * 80 + (sub & 1) * 16);

    const int r_0 = tid >> 1, hf = tid & 1;   // unused (kept minimal): see below
    (void)r_0; (void)hf;

    const int ra = tid >> 2, ca = tid & 3;
    const int rb = (tid + 256) >> 2, cb = ca;

    auto prefetch = [&](int c, int st) {
        const int kc = c * 32;
        uint32_t s0 = sb + (uint32_t)st * STAGEB;
        {
            uint32_t d = s0 + (uint32_t)(ra * 80 + ca * 16);
            size_t ga = ((size_t)(row0 + ra) * 1024 + kc + ca * 8) * 2;
            size_t gb = ((size_t)(col0 + ra) * 1024 + kc + ca * 8) * 2;
            CP_ASYNC16(d,            (const char*)Ahi + ga);
            CP_ASYNC16(d + TILB,     (const char*)Alo + ga);
            CP_ASYNC16(d + 2*TILB,   (const char*)Bhi + gb);
            CP_ASYNC16(d + 3*TILB,   (const char*)Blo + gb);
        }
        {
            uint32_t d = s0 + (uint32_t)(rb * 80 + cb * 16);
            size_t ga = ((size_t)(row0 + rb) * 1024 + kc + cb * 8) * 2;
            size_t gb = ((size_t)(col0 + rb) * 1024 + kc + cb * 8) * 2;
            CP_ASYNC16(d,            (const char*)Ahi + ga);
            CP_ASYNC16(d + TILB,     (const char*)Alo + ga);
            CP_ASYNC16(d + 2*TILB,   (const char*)Bhi + gb);
            CP_ASYNC16(d + 3*TILB,   (const char*)Blo + gb);
        }
    };

    float acc[4][4][4];
    #pragma unroll
    for (int mt = 0; mt < 4; mt++)
        #pragma unroll
        for (int nt = 0; nt < 4; nt++)
            #pragma unroll
            for (int i = 0; i < 4; i++) acc[mt][nt][i] = 0.f;

    prefetch(0, 0); CP_COMMIT();
    prefetch(1, 1); CP_COMMIT();

    const int nk = 32;
    for (int c = 0; c < nk; c++) {
        const int st = c & 1;
        if (c + 1 < nk) { CP_WAIT(1); } else { CP_WAIT(0); }
        __syncthreads();

        const uint32_t s0 = sb + (uint32_t)st * STAGEB;
        const uint32_t aB = s0 + (uint32_t)(wm * 64) * 80;
        const uint32_t bB = s0 + 2 * TILB + (uint32_t)(wn * 32) * 80;

        #pragma unroll
        for (int ks = 0; ks < 2; ks++) {
            const uint32_t kb = ks * 32;
            uint32_t bh[4][2], bl[4][2];
            #pragma unroll
            for (int p = 0; p < 2; p++) {
                uint32_t base = bB + (uint32_t)(p * 16) * 80 + kb;
                LDSM_X4(bh[2*p][0], bh[2*p][1], bh[2*p+1][0], bh[2*p+1][1], base + loffB);
                LDSM_X4(bl[2*p][0], bl[2*p][1], bl[2*p+1][0], bl[2*p+1][1], base + TILB + loffB);
            }
            #pragma unroll
            for (int mt = 0; mt < 4; mt++) {
                uint32_t abase = aB + (uint32_t)(mt * 16) * 80 + kb;
                uint32_t ah[4], al[4];
                LDSM_X4(ah[0], ah[1], ah[2], ah[3], abase + loffA);
                LDSM_X4(al[0], al[1], al[2], al[3], abase + TILB + loffA);
                #pragma unroll
                for (int nt = 0; nt < 4; nt++) {
                    mma_bf16(acc[mt][nt], ah, bh[nt]);
                    mma_bf16(acc[mt][nt], ah, bl[nt]);
                    mma_bf16(acc[mt][nt], al, bh[nt]);
                }
            }
        }
        __syncthreads();
        if (c + 2 < nk) { prefetch(c + 2, st); CP_COMMIT(); }
    }

    #pragma unroll
    for (int mt = 0; mt < 4; mt++) {
        #pragma unroll
        for (int nt = 0; nt < 4; nt++) {
            int r = row0 + wm * 64 + mt * 16 + g;
            int c = col0 + wn * 32 + nt * 8 + 2 * t4;
            float2 v0 = make_float2(acc[mt][nt][0], acc[mt][nt][1]);
            float2 v1 = make_float2(acc[mt][nt][2], acc[mt][nt][3]);
            if (MODE == 0) {
                *(float2*)(C + (size_t)r * 1024 + c)       = v0;
                *(float2*)(C + (size_t)(r + 8) * 1024 + c) = v1;
            } else {
                int b_ = r >> 10, l0 = r & 1023;
                int h_ = c >> 6,  d_ = c & 63;
                size_t base = ((size_t)(b_ * 16 + h_) * 1024) * 64 + d_;
                *(float2*)(C + base + (size_t)l0 * 64)       = v0;
                *(float2*)(C + base + (size_t)(l0 + 8) * 64) = v1;
            }
        }
    }
}

// ===========================================================================
// Even-head attention, tensor-core version (unchanged from R6, passing).
// ===========================================================================
#define SSTR 1032
#define AE_QS   132096
#define AE_KV   140800
#define AE_KVST 18432
#define AE_TL   9216
#define AE_P    177664
#define AE_PST  9216
#define AE_PTL  4608
#define SMEM_EVEN 196096

__global__ __launch_bounds__(512) void attn_even_k(
    const float* __restrict__ Qh, const float* __restrict__ Kh,
    const float* __restrict__ Vh, const float* __restrict__ mask_s,
    float* __restrict__ attn_s, float* __restrict__ out_cat)
{
    extern __shared__ char smem[];
    float* Ssm = (float*)smem;
    float* Qs  = (float*)(smem + AE_QS);
    uint32_t sb;
    asm("{ .reg .u64 u; cvta.to.shared.u64 u, %1; cvt.u32.u64 %0, u; }" : "=r"(sb) : "l"(smem));

    const int qt = blockIdx.x, j = blockIdx.y, b = blockIdx.z;
    const int h = 2 * j;
    const int tid = threadIdx.x;
    const int warp = tid >> 5, lane = tid & 31;
    const int g = lane >> 2, t4 = lane & 3;
    const int mt = warp >> 3, ntw = warp & 7;
    const int m0 = mt * 16, n0 = ntw * 8;
    const size_t headoff = (size_t)(b * 16 + h) * 1024 * 64;
    const float* Qb = Qh + headoff;
    const float* Kb = Kh + headoff;
    const float* Vb = Vh + headoff;
    const int r0 = qt * 32;

    const int krow = tid >> 3, kcol8 = (tid & 7) * 8;
    const int pr = tid >> 4, pc = (tid & 15) * 4;

    {
        int r = tid >> 4, c = (tid & 15) * 4;
        float4 v = *(const float4*)(Qb + (size_t)(r0 + r) * 64 + c);
        *(float4*)&Qs[r * 68 + c] = v;
    }

    float4 fa, fb;
    fa = *(const float4*)(Kb + (size_t)krow * 64 + kcol8);
    fb = *(const float4*)(Kb + (size_t)krow * 64 + kcol8 + 4);
    __syncthreads();

    uint32_t qhF[4][4], qlF[4][4];
    #pragma unroll
    for (int ks = 0; ks < 4; ks++) {
        int kc = ks * 16 + 2 * t4;
        split_pack(Qs[(m0+g)*68 + kc],     Qs[(m0+g)*68 + kc + 1],     qhF[ks][0], qlF[ks][0]);
        split_pack(Qs[(m0+g+8)*68 + kc],   Qs[(m0+g+8)*68 + kc + 1],   qhF[ks][1], qlF[ks][1]);
        split_pack(Qs[(m0+g)*68 + kc + 8], Qs[(m0+g)*68 + kc + 9],     qhF[ks][2], qlF[ks][2]);
        split_pack(Qs[(m0+g+8)*68 + kc+8], Qs[(m0+g+8)*68 + kc + 9],   qhF[ks][3], qlF[ks][3]);
    }

    const int lrow = (lane & 7);
    const uint32_t lsel = (uint32_t)(((lane >> 3) & 1) * 16);

    for (int kt = 0; kt < 16; kt++) {
        const int st = kt & 1;
        {
            uint32_t hw0,hw1,hw2,hw3, lw0,lw1,lw2,lw3;
            split_pack(fa.x, fa.y, hw0, lw0);
            split_pack(fa.z, fa.w, hw1, lw1);
            split_pack(fb.x, fb.y, hw2, lw2);
            split_pack(fb.z, fb.w, hw3, lw3);
            char* dh = smem + AE_KV + st * AE_KVST + krow * 144 + kcol8 * 2;
            *(uint4*)dh            = make_uint4(hw0, hw1, hw2, hw3);
            *(uint4*)(dh + AE_TL)  = make_uint4(lw0, lw1, lw2, lw3);
        }
        if (kt < 15) {
            fa = *(const float4*)(Kb + (size_t)((kt+1)*64 + krow) * 64 + kcol8);
            fb = *(const float4*)(Kb + (size_t)((kt+1)*64 + krow) * 64 + kcol8 + 4);
        }
        __syncthreads();

        float accS[4] = {0.f, 0.f, 0.f, 0.f};
        const uint32_t kb_hi = sb + AE_KV + st * AE_KVST;
        #pragma unroll
        for (int ks = 0; ks < 4; ks++) {
            uint32_t addr = kb_hi + (uint32_t)(n0 + lrow) * 144 + ks * 32 + lsel;
            uint32_t bh[2], bl[2];
            LDSM_X2(bh[0], bh[1], addr);
            LDSM_X2(bl[0], bl[1], addr + AE_TL);
            mma_bf16(accS, qhF[ks], bh);
            mma_bf16(accS, qhF[ks], bl);
            mma_bf16(accS, qlF[ks], bh);
        }
        int cbase = kt * 64 + n0 + 2 * t4;
        *(float2*)&Ssm[(m0+g)*SSTR + cbase]   = make_float2(accS[0], accS[1]);
        *(float2*)&Ssm[(m0+g+8)*SSTR + cbase] = make_float2(accS[2], accS[3]);
    }
    __syncthreads();

    for (int rr = warp * 2; rr < warp * 2 + 2; rr++) {
        const int grow = r0 + rr;
        float* Srow = Ssm + rr * SSTR;
        const float* mrow = mask_s + (size_t)grow * 1024;
        float mx = -1e30f;
        for (int c = lane; c < 1024; c += 32) {
            float s = Srow[c] * 0.125f + mrow[c];
            Srow[c] = s;
            mx = fmaxf(mx, s);
        }
        #pragma unroll
        for (int o = 16; o > 0; o >>= 1) mx = fmaxf(mx, __shfl_xor_sync(0xffffffffu, mx, o));
        float sum = 0.f;
        for (int c = lane; c < 1024; c += 32) {
            float e = __expf(Srow[c] - mx);
            Srow[c] = e;
            sum += e;
        }
        #pragma unroll
        for (int o = 16; o > 0; o >>= 1) sum += __shfl_xor_sync(0xffffffffu, sum, o);
        float inv = 1.f / sum;
        float* arow = attn_s + ((size_t)(b * 8 + j) * 1024 + grow) * 1024;
        for (int c = lane; c < 1024; c += 32) {
            float p = Srow[c] * inv;
            Srow[c] = p;
            arow[c] = p;
        }
    }
    __syncthreads();

    float accO[4] = {0.f, 0.f, 0.f, 0.f};
    fa = *(const float4*)(Vb + (size_t)krow * 64 + kcol8);
    fb = *(const float4*)(Vb + (size_t)krow * 64 + kcol8 + 4);

    const int sub = lane >> 3, r8 = lane & 7;
    const uint32_t poff = (uint32_t)((m0 + r8 + (sub & 1) * 8) * 144 + (sub >> 1) * 16);
    const int vrow = (lane & 15);

    for (int kt = 0; kt < 16; kt++) {
        const int st = kt & 1;
        {
            uint32_t hw0,hw1,hw2,hw3, lw0,lw1,lw2,lw3;
            split_pack(fa.x, fa.y, hw0, lw0);
            split_pack(fa.z, fa.w, hw1, lw1);
            split_pack(fb.x, fb.y, hw2, lw2);
            split_pack(fb.z, fb.w, hw3, lw3);
            char* dh = smem + AE_KV + st * AE_KVST + krow * 144 + kcol8 * 2;
            *(uint4*)dh            = make_uint4(hw0, hw1, hw2, hw3);
            *(uint4*)(dh + AE_TL)  = make_uint4(lw0, lw1, lw2, lw3);
        }
        {
            float4 pv = *(const float4*)&Ssm[pr * SSTR + kt * 64 + pc];
            uint32_t h0, h1, l0, l1;
            split_pack(pv.x, pv.y, h0, l0);
            split_pack(pv.z, pv.w, h1, l1);
            char* dp = smem + AE_P + st * AE_PST + pr * 144 + pc * 2;
            *(uint2*)dp            = make_uint2(h0, h1);
            *(uint2*)(dp + AE_PTL) = make_uint2(l0, l1);
        }
        if (kt < 15) {
            fa = *(const float4*)(Vb + (size_t)((kt+1)*64 + krow) * 64 + kcol8);
            fb = *(const float4*)(Vb + (size_t)((kt+1)*64 + krow) * 64 + kcol8 + 4);
        }
        __syncthreads();

        const uint32_t pb_hi = sb + AE_P + st * AE_PST;
        const uint32_t vb_hi = sb + AE_KV + st * AE_KVST;
        #pragma unroll
        for (int ks = 0; ks < 4; ks++) {
            uint32_t ph[4], pl[4];
            LDSM_X4(ph[0], ph[1], ph[2], ph[3], pb_hi + poff + ks * 32);
            LDSM_X4(pl[0], pl[1], pl[2], pl[3], pb_hi + AE_PTL + poff + ks * 32);
            uint32_t vh[2], vl[2];
            uint32_t vaddr = vb_hi + (uint32_t)(ks * 16 + vrow) * 144 + n0 * 2;
            LDSM_X2_T(vh[0], vh[1], vaddr);
            LDSM_X2_T(vl[0], vl[1], vaddr + AE_TL);
            mma_bf16(accO, ph, vh);
            mma_bf16(accO, ph, vl);
            mma_bf16(accO, pl, vh);
        }
    }

    {
        int c = j * 64 + n0 + 2 * t4;
        *(float2*)(out_cat + ((size_t)b * 1024 + r0 + m0 + g) * 1024 + c)     = make_float2(accO[0], accO[1]);
        *(float2*)(out_cat + ((size_t)b * 1024 + r0 + m0 + g + 8) * 1024 + c) = make_float2(accO[2], accO[3]);
    }
}

// ---------------------------------------------------------------------------
// Odd-head "feature" attention, now 512 threads (same math/layout).
// ---------------------------------------------------------------------------
#define SMEM_FEAT ((2*64*64 + 64*65) * 4)
__global__ __launch_bounds__(512) void attn_feat_k(
    const float* __restrict__ Qh, const float* __restrict__ Kh,
    const float* __restrict__ Vh, const float* __restrict__ mask_f,
    float* __restrict__ attn_f, float* __restrict__ out_cat)
{
    extern __shared__ float sm[];
    float* Qt  = sm;
    float* Kt  = Qt + 4096;
    float* Asm = Kt + 4096;

    const int jp = blockIdx.x, b = blockIdx.y;
    const int h = 2 * jp + 1;
    const int tid = threadIdx.x;
    const size_t headoff = (size_t)(b * 16 + h) * 1024 * 64;
    const float* Qb = Qh + headoff;
    const float* Kb = Kh + headoff;
    const float* Vb = Vh + headoff;

    const int m  = tid & 63;
    const int g8 = tid >> 6;   // 0..7

    float acc[8];
    #pragma unroll
    for (int i = 0; i < 8; i++) acc[i] = 0.f;

    // ---- phase 1: S_f accumulation over 16 L-tiles ----
    for (int lt = 0; lt < 16; lt++) {
        __syncthreads();
        for (int i = tid; i < 1024; i += 512) {
            ((float4*)Qt)[i] = ((const float4*)(Qb + (size_t)lt * 4096))[i];
            ((float4*)Kt)[i] = ((const float4*)(Kb + (size_t)lt * 4096))[i];
        }
        __syncthreads();
        for (int ll = 0; ll < 64; ll++) {
            float kk = Kt[ll * 64 + m];
            #pragma unroll
            for (int i = 0; i < 8; i++)
                acc[i] = fmaf(Qt[ll * 64 + g8 + 8 * i], kk, acc[i]);
        }
    }
    __syncthreads();
    #pragma unroll
    for (int i = 0; i < 8; i++) {
        int n = g8 + 8 * i;
        Asm[n * 65 + m] = acc[i] * 0.125f + mask_f[n * 64 + m];
    }
    __syncthreads();

    // ---- softmax: 16 warps x 4 rows ----
    const int warp = tid >> 5, lane = tid & 31;
    for (int n = warp * 4; n < warp * 4 + 4; n++) {
        float* row = Asm + n * 65;
        float a0 = row[lane], a1 = row[lane + 32];
        float mx = fmaxf(a0, a1);
        #pragma unroll
        for (int o = 16; o > 0; o >>= 1) mx = fmaxf(mx, __shfl_xor_sync(0xffffffffu, mx, o));
        float e0 = __expf(a0 - mx), e1 = __expf(a1 - mx);
        float s = e0 + e1;
        #pragma unroll
        for (int o = 16; o > 0; o >>= 1) s += __shfl_xor_sync(0xffffffffu, s, o);
        float inv = 1.f / s;
        e0 *= inv; e1 *= inv;
        row[lane] = e0; row[lane + 32] = e1;
        float* grow = attn_f + ((size_t)(b * 8 + jp) * 64 + n) * 64;
        grow[lane] = e0; grow[lane + 32] = e1;
    }
    __syncthreads();

    // ---- phase 2: O[l][n] = sum_m V[l][m] * A[n][m] ----
    float* Vt = Qt;
    const int n2 = m;
    for (int lt = 0; lt < 16; lt++) {
        __syncthreads();
        for (int i = tid; i < 1024; i += 512)
            ((float4*)Vt)[i] = ((const float4*)(Vb + (size_t)lt * 4096))[i];
        __syncthreads();

        float accO[8];
        #pragma unroll
        for (int i = 0; i < 8; i++) accO[i] = 0.f;
        for (int mm = 0; mm < 64; mm++) {
            float aa = Asm[n2 * 65 + mm];
            #pragma unroll
            for (int i = 0; i < 8; i++)
                accO[i] = fmaf(Vt[(g8 + 8 * i) * 64 + mm], aa, accO[i]);
        }
        #pragma unroll
        for (int i = 0; i < 8; i++) {
            int ll = g8 + 8 * i;
            out_cat[((size_t)b * 1024 + lt * 64 + ll) * 1024 + (8 + jp) * 64 + n2] = accO[i];
        }
    }
}

// ---------------------------------------------------------------------------
extern "C" void kernel_launch(void* const* d_in, const int* in_sizes, int n_in,
                              void* d_out, int out_size)
{
    const float* q      = (const float*)d_in[0];
    const float* k      = (const float*)d_in[1];
    const float* v      = (const float*)d_in[2];
    const float* mask_s = (const float*)d_in[3];
    const float* mask_f = (const float*)d_in[4];
    const float* Wq     = (const float*)d_in[5];
    const float* Wk     = (const float*)d_in[6];
    const float* Wv     = (const float*)d_in[7];
    const float* Wo     = (const float*)d_in[8];

    float* out    = (float*)d_out;
    float* attn_s = out + OUT_ELEMS;
    float* attn_f = attn_s + ATTNS_ELEMS;

    float *qh, *kh, *vh, *cat;
    __nv_bfloat16 *ahi, *alo, *whi, *wlo;
    cudaGetSymbolAddress((void**)&qh,  g_qh);
    cudaGetSymbolAddress((void**)&kh,  g_kh);
    cudaGetSymbolAddress((void**)&vh,  g_vh);
    cudaGetSymbolAddress((void**)&cat, g_cat);
    cudaGetSymbolAddress((void**)&ahi, g_ahi3);
    cudaGetSymbolAddress((void**)&alo, g_alo3);
    cudaGetSymbolAddress((void**)&whi, g_whi3);
    cudaGetSymbolAddress((void**)&wlo, g_wlo3);

    cudaFuncSetAttribute(attn_even_k, cudaFuncAttributeMaxDynamicSharedMemorySize, SMEM_EVEN);
    cudaFuncSetAttribute(attn_feat_k, cudaFuncAttributeMaxDynamicSharedMemorySize, SMEM_FEAT);
    cudaFuncSetAttribute(gemm_lm_k<0>, cudaFuncAttributeMaxDynamicSharedMemorySize, GSMEM);
    cudaFuncSetAttribute(gemm_lm_k<1>, cudaFuncAttributeMaxDynamicSharedMemorySize, GSMEM);

    dim3 ggrid(DIMn / 128, (Bn * Ln) / 128);      // (8, 128)
    dim3 sgrid3(OUT_ELEMS / (256 * 4), 3);        // merged activation split
    dim3 sgrid(OUT_ELEMS / (256 * 4));            // single (cat)
    dim3 wgrid3(32, 32, 3), wgrid(32, 32), wblk(32, 8);

    const size_t AO = (size_t)OUT_ELEMS;
    const size_t WO = (size_t)DIMn * DIMn;

    // Split all Q/K/V activations + weights upfront (2 launches)
    split_a3_k<<<sgrid3, 256>>>(q, k, v, ahi, alo);
    split_w3_k<<<wgrid3, wblk>>>(Wq, Wk, Wv, whi, wlo);

    // Projections (head-major outputs)
    gemm_lm_k<1><<<ggrid, 256, GSMEM>>>(ahi,          alo,          whi,          wlo,          qh);
    gemm_lm_k<1><<<ggrid, 256, GSMEM>>>(ahi + AO,     alo + AO,     whi + WO,     wlo + WO,     kh);
    gemm_lm_k<1><<<ggrid, 256, GSMEM>>>(ahi + 2*AO,   alo + 2*AO,   whi + 2*WO,   wlo + 2*WO,   vh);

    // Attention
    attn_even_k<<<dim3(32, 8, 16), 512, SMEM_EVEN>>>(qh, kh, vh, mask_s, attn_s, cat);
    attn_feat_k<<<dim3(8, 16), 512, SMEM_FEAT>>>(qh, kh, vh, mask_f, attn_f, cat);

    // Output projection (reuse slice 0 of the split buffers)
    split_a_k<<<sgrid, 256>>>(cat, ahi, alo);
    split_w_k<<<wgrid, wblk>>>(Wo, whi, wlo);
    gemm_lm_k<0><<<ggrid, 256, GSMEM>>>(ahi, alo, whi, wlo, out);
}